// round 8
// baseline (speedup 1.0000x reference)
#include <cuda_runtime.h>
#include <cstdint>

#define BB   4
#define CCH  64
#define HH   180
#define WWD  320
#define HWP  (HH*WWD)
#define NPIX (BB*HWP)
#define NELT ((size_t)NPIX*CCH)

__device__ float g_QlT[(size_t)NPIX*CCH];   // [pix][c]
__device__ float g_Qr [(size_t)NPIX*CCH];   // [c][pix]
__device__ float g_Vl [(size_t)NPIX*CCH];   // [c][pix]
__device__ float g_VrT[(size_t)NPIX*CCH];   // [pix][c]

__device__ __forceinline__ uint32_t f2tf(float x){
    uint32_t u; asm("cvt.rna.tf32.f32 %0, %1;" : "=r"(u) : "f"(x)); return u;
}
__device__ __forceinline__ void mma_tf32(float d[4], const uint32_t a[4], const uint32_t b[2]){
    asm volatile("mma.sync.aligned.m16n8k8.row.col.f32.tf32.tf32.f32 "
                 "{%0,%1,%2,%3}, {%4,%5,%6,%7}, {%8,%9}, {%0,%1,%2,%3};"
                 : "+f"(d[0]), "+f"(d[1]), "+f"(d[2]), "+f"(d[3])
                 : "r"(a[0]), "r"(a[1]), "r"(a[2]), "r"(a[3]), "r"(b[0]), "r"(b[1]));
}

// ---------------- projection via tensor cores (unchanged from R6) ----------------
__global__ __launch_bounds__(256) void proj_mma_kernel(
    const float* __restrict__ x_l, const float* __restrict__ x_r,
    const float* __restrict__ lnw_l, const float* __restrict__ lnb_l,
    const float* __restrict__ lnw_r, const float* __restrict__ lnb_r,
    const float* __restrict__ wq_l,  const float* __restrict__ bq_l,
    const float* __restrict__ wq_r,  const float* __restrict__ bq_r,
    const float* __restrict__ wv_l,  const float* __restrict__ bv_l,
    const float* __restrict__ wv_r,  const float* __restrict__ bv_r)
{
    extern __shared__ float smf[];
    float*    xs = smf;                         // [64][68]
    uint32_t* xt = (uint32_t*)(smf + 4352);     // [64][68]
    uint32_t* wA = (uint32_t*)(smf + 8704);     // [64][68]
    float*    mu_s = smf + 13056;
    float*    rs_s = smf + 13120;
    float*    stf  = (float*)xt;

    int side = blockIdx.x >= 3600;
    int blk  = blockIdx.x - side * 3600;

    const float* x   = side ? x_r   : x_l;
    const float* lnw = side ? lnw_r : lnw_l;
    const float* lnb = side ? lnb_r : lnb_l;
    const float* wq  = side ? wq_r  : wq_l;
    const float* bq  = side ? bq_r  : bq_l;
    const float* wv  = side ? wv_r  : wv_l;
    const float* bv  = side ? bv_r  : bv_l;
    float* Qo = side ? g_Qr  : g_QlT;
    float* Vo = side ? g_VrT : g_Vl;

    int tid = threadIdx.x, lane = tid & 31, wid = tid >> 5;
    int pb  = blk * 64;
    int b   = pb / HWP;
    int q0  = pb - b * HWP;
    const float* xb = x + ((size_t)b * CCH) * HWP + q0;

    #pragma unroll
    for (int i = 0; i < 16; i++) {
        int idx = i * 256 + tid;
        int hi = idx >> 6, lo = idx & 63;
        xs[hi * 68 + lo] = xb[(size_t)hi * HWP + lo];
        wA[hi * 68 + lo] = f2tf(wv[idx]);
    }
    __syncthreads();

    if (tid < 64) {
        float s = 0.f, ss = 0.f;
        #pragma unroll
        for (int c = 0; c < 64; c++) { float v = xs[c * 68 + tid]; s += v; ss += v*v; }
        float m = s * 0.015625f;
        mu_s[tid] = m;
        rs_s[tid] = rsqrtf(ss * 0.015625f - m*m + 1e-6f);
    }
    #pragma unroll
    for (int i = 0; i < 16; i++) {
        int idx = i * 256 + tid;
        int c = idx >> 6, p = idx & 63;
        xt[c * 68 + p] = f2tf(xs[c * 68 + p]);
    }
    __syncthreads();

    int wy = wid >> 1, wx = wid & 1;
    int m0 = wy * 16, n0 = wx * 32;

    float Cv[4][4];
    #pragma unroll
    for (int nt = 0; nt < 4; nt++)
        #pragma unroll
        for (int k = 0; k < 4; k++) Cv[nt][k] = 0.f;
    #pragma unroll
    for (int ks = 0; ks < 8; ks++) {
        uint32_t a[4], bbr[2];
        const uint32_t* pA = wA + (m0 + (lane>>2)) * 68 + ks*8 + (lane&3);
        a[0]=pA[0]; a[1]=pA[8*68]; a[2]=pA[4]; a[3]=pA[8*68+4];
        #pragma unroll
        for (int nt = 0; nt < 4; nt++) {
            const uint32_t* pB = xt + (ks*8 + (lane&3)) * 68 + n0 + nt*8 + (lane>>2);
            bbr[0]=pB[0]; bbr[1]=pB[4*68];
            mma_tf32(Cv[nt], a, bbr);
        }
    }

    int r = m0 + (lane>>2);
    if (side == 0) {
        float b0 = bv[r], b1 = bv[r + 8];
        #pragma unroll
        for (int nt = 0; nt < 4; nt++) {
            int p = n0 + nt*8 + 2*(lane&3);
            *(float2*)&Vo[((size_t)(b*CCH + r)) * HWP + q0 + p] =
                make_float2(Cv[nt][0] + b0, Cv[nt][1] + b0);
            *(float2*)&Vo[((size_t)(b*CCH + r + 8)) * HWP + q0 + p] =
                make_float2(Cv[nt][2] + b1, Cv[nt][3] + b1);
        }
        __syncthreads();
    } else {
        __syncthreads();
        #pragma unroll
        for (int nt = 0; nt < 4; nt++) {
            int p = n0 + nt*8 + 2*(lane&3);
            stf[p * 68 + r]           = Cv[nt][0];
            stf[(p + 1) * 68 + r]     = Cv[nt][1];
            stf[p * 68 + r + 8]       = Cv[nt][2];
            stf[(p + 1) * 68 + r + 8] = Cv[nt][3];
        }
        __syncthreads();
        #pragma unroll
        for (int i = 0; i < 4; i++) {
            int idx = i * 256 + tid;
            int p = idx >> 4, c4 = idx & 15;
            float4 v = *(const float4*)(stf + p * 68 + c4 * 4);
            float4 bb4 = *(const float4*)(bv + c4 * 4);
            *(float4*)&Vo[((size_t)pb + p) * 64 + c4 * 4] =
                make_float4(v.x + bb4.x, v.y + bb4.y, v.z + bb4.z, v.w + bb4.w);
        }
        __syncthreads();
    }

    #pragma unroll
    for (int i = 0; i < 16; i++) {
        int idx = i * 256 + tid;
        wA[(idx >> 6) * 68 + (idx & 63)] = f2tf(wq[idx]);
    }
    #pragma unroll
    for (int i = 0; i < 16; i++) {
        int idx = i * 256 + tid;
        int c = idx >> 6, p = idx & 63;
        xt[c * 68 + p] = f2tf((xs[c * 68 + p] - mu_s[p]) * rs_s[p] * lnw[c] + lnb[c]);
    }
    __syncthreads();

    float Cq[4][4];
    #pragma unroll
    for (int nt = 0; nt < 4; nt++)
        #pragma unroll
        for (int k = 0; k < 4; k++) Cq[nt][k] = 0.f;
    #pragma unroll
    for (int ks = 0; ks < 8; ks++) {
        uint32_t a[4], bbr[2];
        const uint32_t* pA = wA + (m0 + (lane>>2)) * 68 + ks*8 + (lane&3);
        a[0]=pA[0]; a[1]=pA[8*68]; a[2]=pA[4]; a[3]=pA[8*68+4];
        #pragma unroll
        for (int nt = 0; nt < 4; nt++) {
            const uint32_t* pB = xt + (ks*8 + (lane&3)) * 68 + n0 + nt*8 + (lane>>2);
            bbr[0]=pB[0]; bbr[1]=pB[4*68];
            mma_tf32(Cq[nt], a, bbr);
        }
    }

    if (side == 1) {
        float b0 = bq[r], b1 = bq[r + 8];
        #pragma unroll
        for (int nt = 0; nt < 4; nt++) {
            int p = n0 + nt*8 + 2*(lane&3);
            *(float2*)&Qo[((size_t)(b*CCH + r)) * HWP + q0 + p] =
                make_float2(Cq[nt][0] + b0, Cq[nt][1] + b0);
            *(float2*)&Qo[((size_t)(b*CCH + r + 8)) * HWP + q0 + p] =
                make_float2(Cq[nt][2] + b1, Cq[nt][3] + b1);
        }
    } else {
        __syncthreads();
        #pragma unroll
        for (int nt = 0; nt < 4; nt++) {
            int p = n0 + nt*8 + 2*(lane&3);
            stf[p * 68 + r]           = Cq[nt][0];
            stf[(p + 1) * 68 + r]     = Cq[nt][1];
            stf[p * 68 + r + 8]       = Cq[nt][2];
            stf[(p + 1) * 68 + r + 8] = Cq[nt][3];
        }
        __syncthreads();
        #pragma unroll
        for (int i = 0; i < 4; i++) {
            int idx = i * 256 + tid;
            int p = idx >> 4, c4 = idx & 15;
            float4 v = *(const float4*)(stf + p * 68 + c4 * 4);
            float4 bb4 = *(const float4*)(bq + c4 * 4);
            *(float4*)&Qo[((size_t)pb + p) * 64 + c4 * 4] =
                make_float4(v.x + bb4.x, v.y + bb4.y, v.z + bb4.z, v.w + bb4.w);
        }
    }
}

// ---------------- flash-style fused attention per (b,h), 512 threads ----------------
// smem (floats): cs[320] | rs[64] | Qa[64][68] | Kb[64][72] | Vl[64][324] | E[64][324]
#define SM_CS  0
#define SM_RS  320
#define SM_QA  384
#define SM_KB  (SM_QA + 64*68)        // 4736
#define SM_VL  (SM_KB + 64*72)        // 9344
#define SM_E   (SM_VL + 64*324)       // 30080
#define SM_TOT (SM_E + 64*324)        // 50816 words = 203264 B

__global__ __launch_bounds__(512, 1) void fused_flash_kernel(
    const float* __restrict__ x_l, const float* __restrict__ x_r,
    const float* __restrict__ beta, const float* __restrict__ gamma,
    float* __restrict__ out_l, float* __restrict__ out_r)
{
    extern __shared__ float sm[];
    float*    cs  = sm + SM_CS;
    float*    rs  = sm + SM_RS;
    float*    Qa  = sm + SM_QA;      // A-operand strip (stride 68)
    uint32_t* Qau = (uint32_t*)Qa;
    uint32_t* Kb  = (uint32_t*)(sm + SM_KB);  // B chunks (stride 72)
    uint32_t* Vls = (uint32_t*)(sm + SM_VL);  // Vl [64][324]
    float*    Ef  = sm + SM_E;       // E strip [64][324] (tf32 bit patterns)
    uint32_t* Eu  = (uint32_t*)Ef;

    int tid = threadIdx.x, lane = tid & 31, wid = tid >> 5;
    int bh = blockIdx.x, b = bh / HH, h = bh - b * HH;
    size_t pixb = (size_t)b * HWP + h * WWD;
    size_t cmb  = (size_t)b * CCH * HWP + h * WWD;

    int wy = wid >> 2, wx = wid & 3;   // 4x4 warp grid
    int qr = lane >> 2, ql = lane & 3; // quad row/col

    if (tid < 320) cs[tid] = 0.f;

    // Vl resident: [64 c][324 wl]
    {
        const float* src = g_Vl + cmb;
        #pragma unroll
        for (int i = 0; i < 10; i++) {
            int e = i * 512 + tid, c = e / 80, w4 = e % 80;
            float4 v = *(const float4*)(src + (size_t)c * HWP + 4*w4);
            *(uint4*)(Vls + c * 324 + 4*w4) =
                make_uint4(f2tf(v.x), f2tf(v.y), f2tf(v.z), f2tf(v.w));
        }
    }

    // GEMM3 persistent accumulators: out[c 16 rows @ wy][wr 80 cols @ wx]
    float C3[10][4];
    #pragma unroll
    for (int nt = 0; nt < 10; nt++)
        #pragma unroll
        for (int k = 0; k < 4; k++) C3[nt][k] = 0.f;

    for (int s = 0; s < 5; s++) {
        int wl0 = s * 64;
        __syncthreads();   // E/Qa free from previous strip

        // Ql strip -> Qa [64 wl][68 c]
        {
            const float* src = g_QlT + (pixb + wl0) * 64;
            #pragma unroll
            for (int i = 0; i < 2; i++) {
                int e = i * 512 + tid, wl = e >> 4, c4 = e & 15;
                float4 v = *(const float4*)(src + (size_t)wl * 64 + 4*c4);
                *(uint4*)(Qau + wl * 68 + 4*c4) =
                    make_uint4(f2tf(v.x), f2tf(v.y), f2tf(v.z), f2tf(v.w));
            }
        }

        // ---- GEMM1: E[64][320] = exp(0.125 * Ql_strip @ Qr) ----
        for (int t = 0; t < 5; t++) {
            int wr0 = t * 64;
            __syncthreads();  // Kb free
            {   // Qr chunk -> Kb [64 c][72 wr]
                const float* src = g_Qr + cmb + wr0;
                #pragma unroll
                for (int i = 0; i < 2; i++) {
                    int e = i * 512 + tid, c = e >> 4, w4 = e & 15;
                    float4 v = *(const float4*)(src + (size_t)c * HWP + 4*w4);
                    *(uint4*)(Kb + c * 72 + 4*w4) =
                        make_uint4(f2tf(v.x), f2tf(v.y), f2tf(v.z), f2tf(v.w));
                }
            }
            __syncthreads();
            int m0 = wy * 16, n0 = wx * 16;
            float C[2][4];
            #pragma unroll
            for (int nt = 0; nt < 2; nt++)
                #pragma unroll
                for (int k = 0; k < 4; k++) C[nt][k] = 0.f;
            #pragma unroll
            for (int ks = 0; ks < 8; ks++) {
                uint32_t a[4], bbr[2];
                const uint32_t* pA = Qau + (m0 + qr) * 68 + ks*8 + ql;
                a[0]=pA[0]; a[1]=pA[8*68]; a[2]=pA[4]; a[3]=pA[8*68+4];
                #pragma unroll
                for (int nt = 0; nt < 2; nt++) {
                    const uint32_t* pB = Kb + (ks*8 + ql) * 72 + n0 + nt*8 + qr;
                    bbr[0]=pB[0]; bbr[1]=pB[4*72];
                    mma_tf32(C[nt], a, bbr);
                }
            }
            int r = m0 + qr;
            #pragma unroll
            for (int nt = 0; nt < 2; nt++) {
                int col = wr0 + n0 + nt*8 + 2*ql;
                *(uint2*)(Eu + r * 324 + col) = make_uint2(
                    f2tf(__expf(C[nt][0]*0.125f)), f2tf(__expf(C[nt][1]*0.125f)));
                *(uint2*)(Eu + (r+8) * 324 + col) = make_uint2(
                    f2tf(__expf(C[nt][2]*0.125f)), f2tf(__expf(C[nt][3]*0.125f)));
            }
        }
        __syncthreads();  // E strip complete

        // ---- row sums (strip) + col sum accumulation ----
        {   // warp wid -> rows 4*wid .. 4*wid+3
            #pragma unroll
            for (int j = 0; j < 4; j++) {
                int r = 4*wid + j;
                float sum = 0.f;
                #pragma unroll
                for (int k = 0; k < 10; k++) sum += Ef[r * 324 + lane + 32*k];
                #pragma unroll
                for (int o = 16; o > 0; o >>= 1) sum += __shfl_xor_sync(~0u, sum, o);
                if (lane == 0) rs[r] = 1.0f / sum;
            }
            if (tid < 320) {
                float sum = 0.f;
                #pragma unroll 8
                for (int r = 0; r < 64; r++) sum += Ef[r * 324 + tid];
                cs[tid] += sum;
            }
        }

        // ---- GEMM2 (r2l): F[64 wl][64 c] = E_strip @ VrT ----
        float C2[2][4];
        #pragma unroll
        for (int nt = 0; nt < 2; nt++)
            #pragma unroll
            for (int k = 0; k < 4; k++) C2[nt][k] = 0.f;
        for (int kc = 0; kc < 5; kc++) {
            __syncthreads();
            {   // VrT chunk -> Kb [64 wr][72 c]
                const float* src = g_VrT + (pixb + kc*64) * 64;
                #pragma unroll
                for (int i = 0; i < 2; i++) {
                    int e = i * 512 + tid, w = e >> 4, c4 = e & 15;
                    float4 v = *(const float4*)(src + (size_t)w * 64 + 4*c4);
                    *(uint4*)(Kb + w * 72 + 4*c4) =
                        make_uint4(f2tf(v.x), f2tf(v.y), f2tf(v.z), f2tf(v.w));
                }
            }
            __syncthreads();
            int m0 = wy * 16, n0 = wx * 16;
            #pragma unroll
            for (int ks = 0; ks < 8; ks++) {
                uint32_t a[4], bbr[2];
                const uint32_t* pA = Eu + (m0 + qr) * 324 + kc*64 + ks*8 + ql;
                a[0]=pA[0]; a[1]=pA[8*324]; a[2]=pA[4]; a[3]=pA[8*324+4];
                #pragma unroll
                for (int nt = 0; nt < 2; nt++) {
                    const uint32_t* pB = Kb + (ks*8 + ql) * 72 + n0 + nt*8 + qr;
                    bbr[0]=pB[0]; bbr[1]=pB[4*72];
                    mma_tf32(C2[nt], a, bbr);
                }
            }
        }
        __syncthreads();  // Qa (Ql strip) no longer needed; reuse as F staging [c][68 wl]
        {
            int r = wy*16 + qr;            // wl local
            float ri0 = rs[r], ri8 = rs[r + 8];
            #pragma unroll
            for (int nt = 0; nt < 2; nt++) {
                int c = wx*16 + nt*8 + 2*ql;
                Qa[c*68 + r]           = C2[nt][0] * ri0;
                Qa[(c+1)*68 + r]       = C2[nt][1] * ri0;
                Qa[c*68 + r + 8]       = C2[nt][2] * ri8;
                Qa[(c+1)*68 + r + 8]   = C2[nt][3] * ri8;
            }
        }
        __syncthreads();
        {   // out_l = x_l + beta * F   (coalesced)
            const float* xl = x_l + cmb;
            float* ol = out_l + cmb;
            #pragma unroll
            for (int i = 0; i < 2; i++) {
                int e = i * 512 + tid, c = e >> 4, w4 = e & 15;
                float bt = beta[c];
                float4 f = *(const float4*)(Qa + c*68 + 4*w4);
                float4 xv = *(const float4*)(xl + (size_t)c*HWP + wl0 + 4*w4);
                *(float4*)(ol + (size_t)c*HWP + wl0 + 4*w4) = make_float4(
                    xv.x + bt*f.x, xv.y + bt*f.y, xv.z + bt*f.z, xv.w + bt*f.w);
            }
        }

        // ---- GEMM3 (l2r) accumulate: C3 += Vl[:, strip] @ E_strip ----
        {
            int m0 = wy * 16, n0 = wx * 80;
            #pragma unroll
            for (int ks = 0; ks < 8; ks++) {
                uint32_t a[4];
                const uint32_t* pA = Vls + (m0 + qr) * 324 + wl0 + ks*8 + ql;
                a[0]=pA[0]; a[1]=pA[8*324]; a[2]=pA[4]; a[3]=pA[8*324+4];
                #pragma unroll
                for (int nt = 0; nt < 10; nt++) {
                    uint32_t bbr[2];
                    const uint32_t* pB = Eu + (ks*8 + ql) * 324 + n0 + nt*8 + qr;
                    bbr[0]=pB[0]; bbr[1]=pB[4*324];
                    mma_tf32(C3[nt], a, bbr);
                }
            }
        }
        // loop-top __syncthreads protects E/Qa before overwrite
    }

    __syncthreads();
    if (tid < 320) cs[tid] = 1.0f / cs[tid];
    __syncthreads();

    {   // out_r = x_r + gamma * (C3 * cinv)
        const float* xr = x_r + cmb;
        float* orr = out_r + cmb;
        int r = wy*16 + qr;
        float g0 = gamma[r], g1 = gamma[r + 8];
        #pragma unroll
        for (int nt = 0; nt < 10; nt++) {
            int col = wx*80 + nt*8 + 2*ql;
            float ci0 = cs[col], ci1 = cs[col+1];
            float2 x0 = *(const float2*)(xr + (size_t)r*HWP + col);
            *(float2*)(orr + (size_t)r*HWP + col) =
                make_float2(x0.x + g0*ci0*C3[nt][0], x0.y + g0*ci1*C3[nt][1]);
            float2 x1 = *(const float2*)(xr + (size_t)(r+8)*HWP + col);
            *(float2*)(orr + (size_t)(r+8)*HWP + col) =
                make_float2(x1.x + g1*ci0*C3[nt][2], x1.y + g1*ci1*C3[nt][3]);
        }
    }
}

extern "C" void kernel_launch(void* const* d_in, const int* in_sizes, int n_in,
                              void* d_out, int out_size)
{
    const float* x_l    = (const float*)d_in[0];
    const float* x_r    = (const float*)d_in[1];
    const float* ln_l_w = (const float*)d_in[2];
    const float* ln_l_b = (const float*)d_in[3];
    const float* ln_r_w = (const float*)d_in[4];
    const float* ln_r_b = (const float*)d_in[5];
    const float* wq_l   = (const float*)d_in[6];
    const float* bq_l   = (const float*)d_in[7];
    const float* wq_r   = (const float*)d_in[8];
    const float* bq_r   = (const float*)d_in[9];
    const float* wv_l   = (const float*)d_in[10];
    const float* bv_l   = (const float*)d_in[11];
    const float* wv_r   = (const float*)d_in[12];
    const float* bv_r   = (const float*)d_in[13];
    const float* beta   = (const float*)d_in[14];
    const float* gamma  = (const float*)d_in[15];

    float* out_l = (float*)d_out;
    float* out_r = out_l + NELT;

    cudaFuncSetAttribute(proj_mma_kernel,
                         cudaFuncAttributeMaxDynamicSharedMemorySize, 52736);
    cudaFuncSetAttribute(fused_flash_kernel,
                         cudaFuncAttributeMaxDynamicSharedMemorySize, SM_TOT*4);

    proj_mma_kernel<<<7200, 256, 52736>>>(
        x_l, x_r, ln_l_w, ln_l_b, ln_r_w, ln_r_b,
        wq_l, bq_l, wq_r, bq_r, wv_l, bv_l, wv_r, bv_r);
    fused_flash_kernel<<<BB*HH, 512, SM_TOT*4>>>(x_l, x_r, beta, gamma, out_l, out_r);
}

// round 10
// speedup vs baseline: 1.5950x; 1.5950x over previous
#include <cuda_runtime.h>
#include <cstdint>

#define BB   4
#define CCH  64
#define HH   180
#define WWD  320
#define HWP  (HH*WWD)
#define NPIX (BB*HWP)
#define NELT ((size_t)NPIX*CCH)

__device__ float g_QlT[(size_t)NPIX*CCH];   // [pix][c]
__device__ float g_Qr [(size_t)NPIX*CCH];   // [c][pix]
__device__ float g_Vl [(size_t)NPIX*CCH];   // [c][pix]
__device__ float g_Vr [(size_t)NPIX*CCH];   // [c][pix]

__device__ __forceinline__ uint32_t f2tf(float x){
    uint32_t u; asm("cvt.rna.tf32.f32 %0, %1;" : "=r"(u) : "f"(x)); return u;
}
__device__ __forceinline__ uint32_t pack_bf2(float lo, float hi){
    uint32_t u; asm("cvt.rn.bf16x2.f32 %0, %1, %2;" : "=r"(u) : "f"(hi), "f"(lo)); return u;
}
__device__ __forceinline__ void mma_tf32(float d[4], const uint32_t a[4], const uint32_t b[2]){
    asm volatile("mma.sync.aligned.m16n8k8.row.col.f32.tf32.tf32.f32 "
                 "{%0,%1,%2,%3}, {%4,%5,%6,%7}, {%8,%9}, {%0,%1,%2,%3};"
                 : "+f"(d[0]), "+f"(d[1]), "+f"(d[2]), "+f"(d[3])
                 : "r"(a[0]), "r"(a[1]), "r"(a[2]), "r"(a[3]), "r"(b[0]), "r"(b[1]));
}
__device__ __forceinline__ void mma_bf16(float d[4], const uint32_t a[4], const uint32_t b[2]){
    asm volatile("mma.sync.aligned.m16n8k16.row.col.f32.bf16.bf16.f32 "
                 "{%0,%1,%2,%3}, {%4,%5,%6,%7}, {%8,%9}, {%0,%1,%2,%3};"
                 : "+f"(d[0]), "+f"(d[1]), "+f"(d[2]), "+f"(d[3])
                 : "r"(a[0]), "r"(a[1]), "r"(a[2]), "r"(a[3]), "r"(b[0]), "r"(b[1]));
}

// ---------------- projection via tensor cores ----------------
// side 0: Q -> g_QlT [pix][c] (staged), V -> g_Vl [c][pix] direct
// side 1: Q -> g_Qr  [c][pix] direct,  V -> g_Vr [c][pix] direct
__global__ __launch_bounds__(256) void proj_mma_kernel(
    const float* __restrict__ x_l, const float* __restrict__ x_r,
    const float* __restrict__ lnw_l, const float* __restrict__ lnb_l,
    const float* __restrict__ lnw_r, const float* __restrict__ lnb_r,
    const float* __restrict__ wq_l,  const float* __restrict__ bq_l,
    const float* __restrict__ wq_r,  const float* __restrict__ bq_r,
    const float* __restrict__ wv_l,  const float* __restrict__ bv_l,
    const float* __restrict__ wv_r,  const float* __restrict__ bv_r)
{
    extern __shared__ float smf[];
    float*    xs = smf;                         // [64][68]
    uint32_t* xt = (uint32_t*)(smf + 4352);     // [64][68]
    uint32_t* wA = (uint32_t*)(smf + 8704);     // [64][68]
    float*    mu_s = smf + 13056;
    float*    rs_s = smf + 13120;
    float*    stf  = (float*)xt;

    int side = blockIdx.x >= 3600;
    int blk  = blockIdx.x - side * 3600;

    const float* x   = side ? x_r   : x_l;
    const float* lnw = side ? lnw_r : lnw_l;
    const float* lnb = side ? lnb_r : lnb_l;
    const float* wq  = side ? wq_r  : wq_l;
    const float* bq  = side ? bq_r  : bq_l;
    const float* wv  = side ? wv_r  : wv_l;
    const float* bv  = side ? bv_r  : bv_l;
    float* Qo = side ? g_Qr : g_QlT;
    float* Vo = side ? g_Vr : g_Vl;

    int tid = threadIdx.x, lane = tid & 31, wid = tid >> 5;
    int pb  = blk * 64;
    int b   = pb / HWP;
    int q0  = pb - b * HWP;
    const float* xb = x + ((size_t)b * CCH) * HWP + q0;

    #pragma unroll
    for (int i = 0; i < 16; i++) {
        int idx = i * 256 + tid;
        int hi = idx >> 6, lo = idx & 63;
        xs[hi * 68 + lo] = xb[(size_t)hi * HWP + lo];
        wA[hi * 68 + lo] = f2tf(wv[idx]);
    }
    __syncthreads();

    if (tid < 64) {
        float s = 0.f, ss = 0.f;
        #pragma unroll
        for (int c = 0; c < 64; c++) { float v = xs[c * 68 + tid]; s += v; ss += v*v; }
        float m = s * 0.015625f;
        mu_s[tid] = m;
        rs_s[tid] = rsqrtf(ss * 0.015625f - m*m + 1e-6f);
    }
    #pragma unroll
    for (int i = 0; i < 16; i++) {
        int idx = i * 256 + tid;
        int c = idx >> 6, p = idx & 63;
        xt[c * 68 + p] = f2tf(xs[c * 68 + p]);
    }
    __syncthreads();

    int wy = wid >> 1, wx = wid & 1;
    int m0 = wy * 16, n0 = wx * 32;
    int g = lane >> 2, t = lane & 3;

    // ---- V = wv @ x (direct channel-major) ----
    float Cv[4][4];
    #pragma unroll
    for (int nt = 0; nt < 4; nt++)
        #pragma unroll
        for (int k = 0; k < 4; k++) Cv[nt][k] = 0.f;
    #pragma unroll
    for (int ks = 0; ks < 8; ks++) {
        uint32_t a[4], bbr[2];
        const uint32_t* pA = wA + (m0 + g) * 68 + ks*8 + t;
        a[0]=pA[0]; a[1]=pA[8*68]; a[2]=pA[4]; a[3]=pA[8*68+4];
        #pragma unroll
        for (int nt = 0; nt < 4; nt++) {
            const uint32_t* pB = xt + (ks*8 + t) * 68 + n0 + nt*8 + g;
            bbr[0]=pB[0]; bbr[1]=pB[4*68];
            mma_tf32(Cv[nt], a, bbr);
        }
    }
    {
        int r = m0 + g;
        float b0 = bv[r], b1 = bv[r + 8];
        #pragma unroll
        for (int nt = 0; nt < 4; nt++) {
            int p = n0 + nt*8 + 2*t;
            *(float2*)&Vo[((size_t)(b*CCH + r)) * HWP + q0 + p] =
                make_float2(Cv[nt][0] + b0, Cv[nt][1] + b0);
            *(float2*)&Vo[((size_t)(b*CCH + r + 8)) * HWP + q0 + p] =
                make_float2(Cv[nt][2] + b1, Cv[nt][3] + b1);
        }
    }
    __syncthreads();

    #pragma unroll
    for (int i = 0; i < 16; i++) {
        int idx = i * 256 + tid;
        wA[(idx >> 6) * 68 + (idx & 63)] = f2tf(wq[idx]);
    }
    #pragma unroll
    for (int i = 0; i < 16; i++) {
        int idx = i * 256 + tid;
        int c = idx >> 6, p = idx & 63;
        xt[c * 68 + p] = f2tf((xs[c * 68 + p] - mu_s[p]) * rs_s[p] * lnw[c] + lnb[c]);
    }
    __syncthreads();

    // ---- Q = wq @ LN(x) ----
    float Cq[4][4];
    #pragma unroll
    for (int nt = 0; nt < 4; nt++)
        #pragma unroll
        for (int k = 0; k < 4; k++) Cq[nt][k] = 0.f;
    #pragma unroll
    for (int ks = 0; ks < 8; ks++) {
        uint32_t a[4], bbr[2];
        const uint32_t* pA = wA + (m0 + g) * 68 + ks*8 + t;
        a[0]=pA[0]; a[1]=pA[8*68]; a[2]=pA[4]; a[3]=pA[8*68+4];
        #pragma unroll
        for (int nt = 0; nt < 4; nt++) {
            const uint32_t* pB = xt + (ks*8 + t) * 68 + n0 + nt*8 + g;
            bbr[0]=pB[0]; bbr[1]=pB[4*68];
            mma_tf32(Cq[nt], a, bbr);
        }
    }
    int r = m0 + g;
    if (side == 1) {
        float b0 = bq[r], b1 = bq[r + 8];
        #pragma unroll
        for (int nt = 0; nt < 4; nt++) {
            int p = n0 + nt*8 + 2*t;
            *(float2*)&Qo[((size_t)(b*CCH + r)) * HWP + q0 + p] =
                make_float2(Cq[nt][0] + b0, Cq[nt][1] + b0);
            *(float2*)&Qo[((size_t)(b*CCH + r + 8)) * HWP + q0 + p] =
                make_float2(Cq[nt][2] + b1, Cq[nt][3] + b1);
        }
    } else {
        __syncthreads();
        #pragma unroll
        for (int nt = 0; nt < 4; nt++) {
            int p = n0 + nt*8 + 2*t;
            stf[p * 68 + r]           = Cq[nt][0];
            stf[(p + 1) * 68 + r]     = Cq[nt][1];
            stf[p * 68 + r + 8]       = Cq[nt][2];
            stf[(p + 1) * 68 + r + 8] = Cq[nt][3];
        }
        __syncthreads();
        #pragma unroll
        for (int i = 0; i < 4; i++) {
            int idx = i * 256 + tid;
            int p = idx >> 4, c4 = idx & 15;
            float4 v = *(const float4*)(stf + p * 68 + c4 * 4);
            float4 bb4 = *(const float4*)(bq + c4 * 4);
            *(float4*)&Qo[((size_t)pb + p) * 64 + c4 * 4] =
                make_float4(v.x + bb4.x, v.y + bb4.y, v.z + bb4.z, v.w + bb4.w);
        }
    }
}

// ---------------- flash fused attention v2: resident Qr/Vr, bf16 E ----------------
// smem words: cs[320] rs[64] | Qr tf32 [64][328] | Qa tf32 [64][68]
//             | Vr bf16 [64][164w] | Vl bf16 strip [64][36w] | E bf16 [64][164w]
#define SM_CS  0
#define SM_RS  320
#define SM_QR  384
#define SM_QA  (SM_QR + 64*328)     // 21376
#define SM_VR  (SM_QA + 64*68)      // 25728
#define SM_VLS (SM_VR + 64*164)     // 36224
#define SM_EB  (SM_VLS + 64*36)     // 38528
#define SM_TOTW (SM_EB + 64*164)    // 49024 words = 196096 B

__global__ __launch_bounds__(512, 1) void fused_flash2_kernel(
    const float* __restrict__ x_l, const float* __restrict__ x_r,
    const float* __restrict__ beta, const float* __restrict__ gamma,
    float* __restrict__ out_l, float* __restrict__ out_r)
{
    extern __shared__ float sm[];
    float*    cs   = sm + SM_CS;
    float*    rs   = sm + SM_RS;
    uint32_t* Qru  = (uint32_t*)(sm + SM_QR);
    uint32_t* Qau  = (uint32_t*)(sm + SM_QA);
    uint32_t* VrBw = (uint32_t*)(sm + SM_VR);
    uint32_t* VlBw = (uint32_t*)(sm + SM_VLS);
    uint32_t* Ew   = (uint32_t*)(sm + SM_EB);
    const unsigned short* Ehs = (const unsigned short*)Ew;

    int tid = threadIdx.x, lane = tid & 31, wid = tid >> 5;
    int g = lane >> 2, t = lane & 3;
    int bh = blockIdx.x, b = bh / HH, h = bh - b * HH;
    size_t pixb = (size_t)b * HWP + h * WWD;
    size_t cmb  = (size_t)b * CCH * HWP + h * WWD;

    // init: Qr resident (tf32), Vr resident (bf16), cs = 0
    if (tid < 320) cs[tid] = 0.f;
    {
        const float* src = g_Qr + cmb;
        #pragma unroll
        for (int i = 0; i < 10; i++) {
            int e = i * 512 + tid, c = e / 80, w4 = e % 80;
            float4 v = *(const float4*)(src + (size_t)c * HWP + 4*w4);
            *(uint4*)(Qru + c * 328 + 4*w4) =
                make_uint4(f2tf(v.x), f2tf(v.y), f2tf(v.z), f2tf(v.w));
        }
        const float* srv = g_Vr + cmb;
        #pragma unroll
        for (int i = 0; i < 10; i++) {
            int e = i * 512 + tid, c = e / 80, w4 = e % 80;
            float4 v = *(const float4*)(srv + (size_t)c * HWP + 4*w4);
            *(uint2*)(VrBw + c * 164 + 2*w4) =
                make_uint2(pack_bf2(v.x, v.y), pack_bf2(v.z, v.w));
        }
    }

    // persistent l2r accumulators: C3[mt 2][nt 5][4]; m0 = wy3*32, n0 = wx3*40
    int wy3 = wid & 1, wx3 = wid >> 1;
    float C3[2][5][4];
    #pragma unroll
    for (int mt = 0; mt < 2; mt++)
        #pragma unroll
        for (int nt = 0; nt < 5; nt++)
            #pragma unroll
            for (int k = 0; k < 4; k++) C3[mt][nt][k] = 0.f;

    for (int s = 0; s < 5; s++) {
        int wl0 = s * 64;

        // strip loads: Qa (tf32), Vl strip (bf16), rs = 0
        if (tid < 64) rs[tid] = 0.f;
        {
            const float* src = g_QlT + (pixb + wl0) * 64;
            #pragma unroll
            for (int i = 0; i < 2; i++) {
                int e = i * 512 + tid, wl = e >> 4, c4 = e & 15;
                float4 v = *(const float4*)(src + (size_t)wl * 64 + 4*c4);
                *(uint4*)(Qau + wl * 68 + 4*c4) =
                    make_uint4(f2tf(v.x), f2tf(v.y), f2tf(v.z), f2tf(v.w));
            }
            const float* srv = g_Vl + cmb + wl0;
            #pragma unroll
            for (int i = 0; i < 2; i++) {
                int e = i * 512 + tid, c = e >> 4, w4 = e & 15;
                float4 v = *(const float4*)(srv + (size_t)c * HWP + 4*w4);
                *(uint2*)(VlBw + c * 36 + 2*w4) =
                    make_uint2(pack_bf2(v.x, v.y), pack_bf2(v.z, v.w));
            }
        }
        __syncthreads();   // (A) strip operands ready; prev-strip E free

        // ---- GEMM1 (tf32): E = exp(0.125 * Ql_strip @ Qr), bf16 store + sums ----
        {
            int wy1 = wid >> 3, wx1 = wid & 7;       // m 2x32, n 8x40
            int m0 = wy1 * 32, n0 = wx1 * 40;
            float C1[2][5][4];
            #pragma unroll
            for (int mt = 0; mt < 2; mt++)
                #pragma unroll
                for (int nt = 0; nt < 5; nt++)
                    #pragma unroll
                    for (int k = 0; k < 4; k++) C1[mt][nt][k] = 0.f;
            #pragma unroll
            for (int ks = 0; ks < 8; ks++) {
                uint32_t a[2][4], bbr[2];
                #pragma unroll
                for (int mt = 0; mt < 2; mt++) {
                    const uint32_t* pA = Qau + (m0 + mt*16 + g) * 68 + ks*8 + t;
                    a[mt][0]=pA[0]; a[mt][1]=pA[8*68]; a[mt][2]=pA[4]; a[mt][3]=pA[8*68+4];
                }
                #pragma unroll
                for (int nt = 0; nt < 5; nt++) {
                    const uint32_t* pB = Qru + (ks*8 + t) * 328 + n0 + nt*8 + g;
                    bbr[0]=pB[0]; bbr[1]=pB[4*328];
                    #pragma unroll
                    for (int mt = 0; mt < 2; mt++) mma_tf32(C1[mt][nt], a[mt], bbr);
                }
            }
            float rsum[2][2];
            rsum[0][0]=rsum[0][1]=rsum[1][0]=rsum[1][1]=0.f;
            #pragma unroll
            for (int nt = 0; nt < 5; nt++) {
                float cv0 = 0.f, cv1 = 0.f;
                #pragma unroll
                for (int mt = 0; mt < 2; mt++) {
                    float e0 = __expf(C1[mt][nt][0]*0.125f);
                    float e1 = __expf(C1[mt][nt][1]*0.125f);
                    float e2 = __expf(C1[mt][nt][2]*0.125f);
                    float e3 = __expf(C1[mt][nt][3]*0.125f);
                    int row = m0 + mt*16 + g;
                    int cw  = wx1*20 + nt*4 + t;   // word col = (n0 + nt*8 + 2t)/2
                    Ew[row * 164 + cw]       = pack_bf2(e0, e1);
                    Ew[(row + 8) * 164 + cw] = pack_bf2(e2, e3);
                    rsum[mt][0] += e0 + e1;
                    rsum[mt][1] += e2 + e3;
                    cv0 += e0 + e2;
                    cv1 += e1 + e3;
                }
                cv0 += __shfl_xor_sync(~0u, cv0, 4);
                cv0 += __shfl_xor_sync(~0u, cv0, 8);
                cv0 += __shfl_xor_sync(~0u, cv0, 16);
                cv1 += __shfl_xor_sync(~0u, cv1, 4);
                cv1 += __shfl_xor_sync(~0u, cv1, 8);
                cv1 += __shfl_xor_sync(~0u, cv1, 16);
                if (g == 0) {
                    int col = n0 + nt*8 + 2*t;
                    atomicAdd(&cs[col], cv0);
                    atomicAdd(&cs[col + 1], cv1);
                }
            }
            #pragma unroll
            for (int mt = 0; mt < 2; mt++) {
                float s0 = rsum[mt][0], s1 = rsum[mt][1];
                s0 += __shfl_xor_sync(~0u, s0, 1); s0 += __shfl_xor_sync(~0u, s0, 2);
                s1 += __shfl_xor_sync(~0u, s1, 1); s1 += __shfl_xor_sync(~0u, s1, 2);
                if (t == 0) {
                    atomicAdd(&rs[m0 + mt*16 + g], s0);
                    atomicAdd(&rs[m0 + mt*16 + g + 8], s1);
                }
            }
        }
        __syncthreads();   // (B) E + rs complete

        // ---- GEMM2' (bf16): F^T[c][wl] = Vr[c][wr] @ E[wl][wr]^T, K=320 ----
        {
            int wy2 = wid >> 2, wx2 = wid & 3;   // m 4x16, n 4x16
            int m0 = wy2 * 16, n0 = wx2 * 16;
            float C2[2][4];
            #pragma unroll
            for (int nt = 0; nt < 2; nt++)
                #pragma unroll
                for (int k = 0; k < 4; k++) C2[nt][k] = 0.f;
            #pragma unroll 5
            for (int ks = 0; ks < 20; ks++) {
                uint32_t a[4], bbr[2];
                const uint32_t* pA = VrBw + (m0 + g) * 164 + ks*8 + t;
                a[0]=pA[0]; a[1]=pA[8*164]; a[2]=pA[4]; a[3]=pA[8*164+4];
                #pragma unroll
                for (int nt = 0; nt < 2; nt++) {
                    const uint32_t* pB = Ew + (n0 + nt*8 + g) * 164 + ks*8 + t;
                    bbr[0]=pB[0]; bbr[1]=pB[4];
                    mma_bf16(C2[nt], a, bbr);
                }
            }
            // epilogue: out_l[c][wl0+wl] = x_l + beta[c] * C2 / rs[wl]
            const float* xl = x_l + cmb;
            float* ol = out_l + cmb;
            int c0 = m0 + g;
            float bt0 = beta[c0], bt1 = beta[c0 + 8];
            #pragma unroll
            for (int nt = 0; nt < 2; nt++) {
                int wl = n0 + nt*8 + 2*t;
                float ri0 = __fdividef(1.f, rs[wl]);
                float ri1 = __fdividef(1.f, rs[wl + 1]);
                float2 x0 = *(const float2*)(xl + (size_t)c0*HWP + wl0 + wl);
                *(float2*)(ol + (size_t)c0*HWP + wl0 + wl) = make_float2(
                    x0.x + bt0*ri0*C2[nt][0], x0.y + bt0*ri1*C2[nt][1]);
                float2 x1 = *(const float2*)(xl + (size_t)(c0+8)*HWP + wl0 + wl);
                *(float2*)(ol + (size_t)(c0+8)*HWP + wl0 + wl) = make_float2(
                    x1.x + bt1*ri0*C2[nt][2], x1.y + bt1*ri1*C2[nt][3]);
            }
        }

        // ---- GEMM3 (bf16) accumulate: C3 += Vl_strip[c][wl] @ E[wl][wr] ----
        {
            int m0 = wy3 * 32, n0 = wx3 * 40;
            #pragma unroll
            for (int ks = 0; ks < 4; ks++) {
                uint32_t a[2][4];
                #pragma unroll
                for (int mt = 0; mt < 2; mt++) {
                    const uint32_t* pA = VlBw + (m0 + mt*16 + g) * 36 + ks*8 + t;
                    a[mt][0]=pA[0]; a[mt][1]=pA[8*36]; a[mt][2]=pA[4]; a[mt][3]=pA[8*36+4];
                }
                int k0 = ks * 16;
                #pragma unroll
                for (int nt = 0; nt < 5; nt++) {
                    int n = n0 + nt*8 + g;
                    uint32_t bbr[2];
                    bbr[0] = (uint32_t)Ehs[(k0 + 2*t) * 328 + n]
                           | ((uint32_t)Ehs[(k0 + 2*t + 1) * 328 + n] << 16);
                    bbr[1] = (uint32_t)Ehs[(k0 + 2*t + 8) * 328 + n]
                           | ((uint32_t)Ehs[(k0 + 2*t + 9) * 328 + n] << 16);
                    #pragma unroll
                    for (int mt = 0; mt < 2; mt++) mma_bf16(C3[mt][nt], a[mt], bbr);
                }
            }
        }
        __syncthreads();   // (C) strip done: E/Qa/VlB/rs reusable
    }

    if (tid < 320) cs[tid] = __fdividef(1.f, cs[tid]);
    __syncthreads();

    // final epilogue: out_r[c][wr] = x_r + gamma[c] * C3 * cinv[wr]
    {
        const float* xr = x_r + cmb;
        float* orr = out_r + cmb;
        int m0 = wy3 * 32, n0 = wx3 * 40;
        #pragma unroll
        for (int mt = 0; mt < 2; mt++) {
            int c0 = m0 + mt*16 + g;
            float g0 = gamma[c0], g1 = gamma[c0 + 8];
            #pragma unroll
            for (int nt = 0; nt < 5; nt++) {
                int col = n0 + nt*8 + 2*t;
                float ci0 = cs[col], ci1 = cs[col + 1];
                float2 x0 = *(const float2*)(xr + (size_t)c0*HWP + col);
                *(float2*)(orr + (size_t)c0*HWP + col) = make_float2(
                    x0.x + g0*ci0*C3[mt][nt][0], x0.y + g0*ci1*C3[mt][nt][1]);
                float2 x1 = *(const float2*)(xr + (size_t)(c0+8)*HWP + col);
                *(float2*)(orr + (size_t)(c0+8)*HWP + col) = make_float2(
                    x1.x + g1*ci0*C3[mt][nt][2], x1.y + g1*ci1*C3[mt][nt][3]);
            }
        }
    }
}

extern "C" void kernel_launch(void* const* d_in, const int* in_sizes, int n_in,
                              void* d_out, int out_size)
{
    const float* x_l    = (const float*)d_in[0];
    const float* x_r    = (const float*)d_in[1];
    const float* ln_l_w = (const float*)d_in[2];
    const float* ln_l_b = (const float*)d_in[3];
    const float* ln_r_w = (const float*)d_in[4];
    const float* ln_r_b = (const float*)d_in[5];
    const float* wq_l   = (const float*)d_in[6];
    const float* bq_l   = (const float*)d_in[7];
    const float* wq_r   = (const float*)d_in[8];
    const float* bq_r   = (const float*)d_in[9];
    const float* wv_l   = (const float*)d_in[10];
    const float* bv_l   = (const float*)d_in[11];
    const float* wv_r   = (const float*)d_in[12];
    const float* bv_r   = (const float*)d_in[13];
    const float* beta   = (const float*)d_in[14];
    const float* gamma  = (const float*)d_in[15];

    float* out_l = (float*)d_out;
    float* out_r = out_l + NELT;

    cudaFuncSetAttribute(proj_mma_kernel,
                         cudaFuncAttributeMaxDynamicSharedMemorySize, 52736);
    cudaFuncSetAttribute(fused_flash2_kernel,
                         cudaFuncAttributeMaxDynamicSharedMemorySize, SM_TOTW*4);

    proj_mma_kernel<<<7200, 256, 52736>>>(
        x_l, x_r, ln_l_w, ln_l_b, ln_r_w, ln_r_b,
        wq_l, bq_l, wq_r, bq_r, wv_l, bv_l, wv_r, bv_r);
    fused_flash2_kernel<<<BB*HH, 512, SM_TOTW*4>>>(x_l, x_r, beta, gamma, out_l, out_r);
}